// round 2
// baseline (speedup 1.0000x reference)
#include <cuda_runtime.h>

// Rodrigues rotation matrix from two vectors, 4 elements per thread,
// fully float4-vectorized I/O.
//
// Per element: a = v1/|v1|, b = v2/|v2|, v = a x b, c = a.b, s2 = |v|^2
//   R = I + K + (v v^T - s2 I) * (1-c)/s2      (K = skew(v))
// Degenerate (s < 1e-30): c>0 -> I ; c<0 -> 180deg rotation about axis perp to a.

#define S_EPS 1e-30f
#define RTOL_ 1e-5f
#define ATOL_ 1e-8f

__global__ __launch_bounds__(256) void rodrigues_kernel(
    const float4* __restrict__ g1,
    const float4* __restrict__ g2,
    float4* __restrict__ gout,
    int n4)
{
    int t = blockIdx.x * blockDim.x + threadIdx.x;
    if (t >= n4) return;

    // 4 elements = 12 floats per input = 3 float4 loads each
    float4 p0 = g1[3 * t + 0];
    float4 p1 = g1[3 * t + 1];
    float4 p2 = g1[3 * t + 2];
    float4 q0 = g2[3 * t + 0];
    float4 q1 = g2[3 * t + 1];
    float4 q2 = g2[3 * t + 2];

    float A[12]  = {p0.x, p0.y, p0.z, p0.w, p1.x, p1.y, p1.z, p1.w,
                    p2.x, p2.y, p2.z, p2.w};
    float Bv[12] = {q0.x, q0.y, q0.z, q0.w, q1.x, q1.y, q1.z, q1.w,
                    q2.x, q2.y, q2.z, q2.w};
    float O[36];

#pragma unroll
    for (int e = 0; e < 4; e++) {
        float ax = A[3 * e + 0], ay = A[3 * e + 1], az = A[3 * e + 2];
        float bx = Bv[3 * e + 0], by = Bv[3 * e + 1], bz = Bv[3 * e + 2];

        float ra = rsqrtf(ax * ax + ay * ay + az * az);
        ax *= ra; ay *= ra; az *= ra;
        float rb = rsqrtf(bx * bx + by * by + bz * bz);
        bx *= rb; by *= rb; bz *= rb;

        // v = a x b
        float vx = ay * bz - az * by;
        float vy = az * bx - ax * bz;
        float vz = ax * by - ay * bx;
        float c  = ax * bx + ay * by + az * bz;
        float s2 = vx * vx + vy * vy + vz * vz;

        // coef = (1-c)/s2_safe  (s2_safe = 1 when s2 == 0)
        float coef = (1.0f - c) / (s2 > 0.0f ? s2 : 1.0f);

        // R = I + K + (v v^T - s2 I) * coef
        float r00 = 1.0f + (vx * vx - s2) * coef;
        float r01 = vx * vy * coef - vz;
        float r02 = vx * vz * coef + vy;
        float r10 = vx * vy * coef + vz;
        float r11 = 1.0f + (vy * vy - s2) * coef;
        float r12 = vy * vz * coef - vx;
        float r20 = vx * vz * coef - vy;
        float r21 = vy * vz * coef + vx;
        float r22 = 1.0f + (vz * vz - s2) * coef;

        float s = sqrtf(s2);
        if (s < S_EPS) {
            if (c > 0.0f) {
                // identity
                r00 = 1.0f; r01 = 0.0f; r02 = 0.0f;
                r10 = 0.0f; r11 = 1.0f; r12 = 0.0f;
                r20 = 0.0f; r21 = 0.0f; r22 = 1.0f;
            } else if (c < 0.0f) {
                // 180-degree rotation about axis perpendicular to a
                bool close_e1 = (fabsf(ax - 1.0f) <= ATOL_ + RTOL_) &&
                                (fabsf(ay) <= ATOL_) &&
                                (fabsf(az) <= ATOL_);
                float ex = close_e1 ? 0.0f : 1.0f;
                float ey = close_e1 ? 1.0f : 0.0f;
                // perp = a x axis, axis = (ex, ey, 0)
                float px = -az * ey;
                float py =  az * ex;
                float pz = ax * ey - ay * ex;
                float pn = sqrtf(px * px + py * py + pz * pz);
                float inv = (pn > 0.0f) ? (1.0f / pn) : 1.0f;
                px *= inv; py *= inv; pz *= inv;
                // R180 = I + 2*(p p^T - I) = 2 p p^T - I
                r00 = 2.0f * px * px - 1.0f;
                r01 = 2.0f * px * py;
                r02 = 2.0f * px * pz;
                r10 = 2.0f * py * px;
                r11 = 2.0f * py * py - 1.0f;
                r12 = 2.0f * py * pz;
                r20 = 2.0f * pz * px;
                r21 = 2.0f * pz * py;
                r22 = 2.0f * pz * pz - 1.0f;
            }
        }

        O[9 * e + 0] = r00; O[9 * e + 1] = r01; O[9 * e + 2] = r02;
        O[9 * e + 3] = r10; O[9 * e + 4] = r11; O[9 * e + 5] = r12;
        O[9 * e + 6] = r20; O[9 * e + 7] = r21; O[9 * e + 8] = r22;
    }

    // 36 floats out = 9 float4 stores
#pragma unroll
    for (int j = 0; j < 9; j++) {
        gout[9 * t + j] = make_float4(O[4 * j + 0], O[4 * j + 1],
                                      O[4 * j + 2], O[4 * j + 3]);
    }
}

extern "C" void kernel_launch(void* const* d_in, const int* in_sizes, int n_in,
                              void* d_out, int out_size)
{
    const float4* v1 = (const float4*)d_in[0];
    const float4* v2 = (const float4*)d_in[1];
    float4* out = (float4*)d_out;

    int n_elems = in_sizes[0] / 3;   // 4,194,304
    int n4 = n_elems / 4;            // 1,048,576 threads (n_elems % 4 == 0)

    int threads = 256;
    int blocks = (n4 + threads - 1) / threads;
    rodrigues_kernel<<<blocks, threads>>>(v1, v2, out, n4);
}

// round 3
// speedup vs baseline: 1.4246x; 1.4246x over previous
#include <cuda_runtime.h>

// Rodrigues rotation matrix from two vectors.
// 4 elements/thread, 256 threads/block => 1024 elements/block.
// All GMEM traffic is staged through SMEM so that global loads/stores are
// perfectly coalesced (lane i <-> float4 i); the strided per-element access
// happens in SMEM where stride-48B reads and stride-144B writes are
// bank-conflict-free for 128-bit accesses.

#define S_EPS 1e-30f
#define RTOL_ 1e-5f
#define ATOL_ 1e-8f

#define TPB 256
#define ELEMS_PER_BLOCK (TPB * 4)          // 1024
#define IN_F4_PER_BLOCK (TPB * 3)          // 768 float4 per input per block
#define OUT_F4_PER_BLOCK (TPB * 9)         // 2304 float4 out per block

__global__ __launch_bounds__(TPB) void rodrigues_kernel(
    const float4* __restrict__ g1,
    const float4* __restrict__ g2,
    float4* __restrict__ gout)
{
    __shared__ float4 sbuf[OUT_F4_PER_BLOCK];   // 36 KB, reused in+out

    const int tid = threadIdx.x;
    const int blk = blockIdx.x;

    // ---- Phase 1: coalesced global loads into smem ----
    const float4* src1 = g1 + (size_t)blk * IN_F4_PER_BLOCK;
    const float4* src2 = g2 + (size_t)blk * IN_F4_PER_BLOCK;
#pragma unroll
    for (int k = 0; k < 3; k++)
        sbuf[k * TPB + tid] = src1[k * TPB + tid];
#pragma unroll
    for (int k = 0; k < 3; k++)
        sbuf[IN_F4_PER_BLOCK + k * TPB + tid] = src2[k * TPB + tid];
    __syncthreads();

    // ---- Phase 2: strided smem reads (conflict-free), compute ----
    float4 p0 = sbuf[3 * tid + 0];
    float4 p1 = sbuf[3 * tid + 1];
    float4 p2 = sbuf[3 * tid + 2];
    float4 q0 = sbuf[IN_F4_PER_BLOCK + 3 * tid + 0];
    float4 q1 = sbuf[IN_F4_PER_BLOCK + 3 * tid + 1];
    float4 q2 = sbuf[IN_F4_PER_BLOCK + 3 * tid + 2];
    __syncthreads();   // inputs consumed; smem will be overwritten with output

    float A[12]  = {p0.x, p0.y, p0.z, p0.w, p1.x, p1.y, p1.z, p1.w,
                    p2.x, p2.y, p2.z, p2.w};
    float Bv[12] = {q0.x, q0.y, q0.z, q0.w, q1.x, q1.y, q1.z, q1.w,
                    q2.x, q2.y, q2.z, q2.w};
    float O[36];

#pragma unroll
    for (int e = 0; e < 4; e++) {
        float ax = A[3 * e + 0], ay = A[3 * e + 1], az = A[3 * e + 2];
        float bx = Bv[3 * e + 0], by = Bv[3 * e + 1], bz = Bv[3 * e + 2];

        float ra = rsqrtf(ax * ax + ay * ay + az * az);
        ax *= ra; ay *= ra; az *= ra;
        float rb = rsqrtf(bx * bx + by * by + bz * bz);
        bx *= rb; by *= rb; bz *= rb;

        // v = a x b
        float vx = ay * bz - az * by;
        float vy = az * bx - ax * bz;
        float vz = ax * by - ay * bx;
        float c  = ax * bx + ay * by + az * bz;
        float s2 = vx * vx + vy * vy + vz * vz;

        float coef = (1.0f - c) / (s2 > 0.0f ? s2 : 1.0f);

        // R = I + K + (v v^T - s2 I) * coef
        float r00 = 1.0f + (vx * vx - s2) * coef;
        float r01 = vx * vy * coef - vz;
        float r02 = vx * vz * coef + vy;
        float r10 = vx * vy * coef + vz;
        float r11 = 1.0f + (vy * vy - s2) * coef;
        float r12 = vy * vz * coef - vx;
        float r20 = vx * vz * coef - vy;
        float r21 = vy * vz * coef + vx;
        float r22 = 1.0f + (vz * vz - s2) * coef;

        float s = sqrtf(s2);
        if (s < S_EPS) {
            if (c > 0.0f) {
                r00 = 1.0f; r01 = 0.0f; r02 = 0.0f;
                r10 = 0.0f; r11 = 1.0f; r12 = 0.0f;
                r20 = 0.0f; r21 = 0.0f; r22 = 1.0f;
            } else if (c < 0.0f) {
                bool close_e1 = (fabsf(ax - 1.0f) <= ATOL_ + RTOL_) &&
                                (fabsf(ay) <= ATOL_) &&
                                (fabsf(az) <= ATOL_);
                float ex = close_e1 ? 0.0f : 1.0f;
                float ey = close_e1 ? 1.0f : 0.0f;
                float px = -az * ey;
                float py =  az * ex;
                float pz = ax * ey - ay * ex;
                float pn = sqrtf(px * px + py * py + pz * pz);
                float inv = (pn > 0.0f) ? (1.0f / pn) : 1.0f;
                px *= inv; py *= inv; pz *= inv;
                r00 = 2.0f * px * px - 1.0f;
                r01 = 2.0f * px * py;
                r02 = 2.0f * px * pz;
                r10 = 2.0f * py * px;
                r11 = 2.0f * py * py - 1.0f;
                r12 = 2.0f * py * pz;
                r20 = 2.0f * pz * px;
                r21 = 2.0f * pz * py;
                r22 = 2.0f * pz * pz - 1.0f;
            }
        }

        O[9 * e + 0] = r00; O[9 * e + 1] = r01; O[9 * e + 2] = r02;
        O[9 * e + 3] = r10; O[9 * e + 4] = r11; O[9 * e + 5] = r12;
        O[9 * e + 6] = r20; O[9 * e + 7] = r21; O[9 * e + 8] = r22;
    }

    // ---- Phase 3: strided smem writes (conflict-free) ----
#pragma unroll
    for (int j = 0; j < 9; j++)
        sbuf[9 * tid + j] = make_float4(O[4 * j + 0], O[4 * j + 1],
                                        O[4 * j + 2], O[4 * j + 3]);
    __syncthreads();

    // ---- Phase 4: coalesced global stores ----
    float4* dst = gout + (size_t)blk * OUT_F4_PER_BLOCK;
#pragma unroll
    for (int k = 0; k < 9; k++)
        dst[k * TPB + tid] = sbuf[k * TPB + tid];
}

extern "C" void kernel_launch(void* const* d_in, const int* in_sizes, int n_in,
                              void* d_out, int out_size)
{
    const float4* v1 = (const float4*)d_in[0];
    const float4* v2 = (const float4*)d_in[1];
    float4* out = (float4*)d_out;

    int n_elems = in_sizes[0] / 3;                 // 4,194,304
    int blocks = n_elems / ELEMS_PER_BLOCK;        // 4096 (exact)

    rodrigues_kernel<<<blocks, TPB>>>(v1, v2, out);
}